// round 2
// baseline (speedup 1.0000x reference)
#include <cuda_runtime.h>

// Problem constants
#define BB   2
#define CC   64
#define HH   256
#define WWI  256
#define HWN  (HH*WWI)      // 65536
#define IC1  128
#define OC1  128
#define OC2  576
#define EPSF 1e-5f
#define ROWL 260           // padded tile row (258 used)

typedef unsigned long long ull;

__device__ __forceinline__ void fma2(ull& d, ull a, ull b) {
    asm("fma.rn.f32x2 %0, %1, %2, %0;" : "+l"(d) : "l"(a), "l"(b));
}
__device__ __forceinline__ ull pack2(float lo, float hi) {
    ull r; asm("mov.b64 %0, {%1, %2};" : "=l"(r) : "f"(lo), "f"(hi)); return r;
}
__device__ __forceinline__ void unpack2(ull v, float& lo, float& hi) {
    asm("mov.b64 {%0, %1}, %2;" : "=f"(lo), "=f"(hi) : "l"(v));
}

// ---------------- scratch (static device globals; no allocations) ----------
__device__ float g_t[BB*OC1*HWN];       // conv1 outputs (relu): ch 0-63 = cw branch, 64-127 = dw branch
__device__ float g_w1t[IC1*9*OC1];      // conv1 weights transposed: [red=ic*9+r*3+s][oc]
__device__ float g_w2t[CC*9*OC2];       // conv2 weights transposed: [red][oc]
__device__ float g_y[BB*CC*HWN];        // guided-conv output
__device__ float g_z[BB*CC*HWN];        // einsum output (pre-BN)
__device__ float g_hmean[BB*CC];
__device__ float g_dwT[BB*CC*CC];       // [b][c][o]
__device__ float g_sum[CC];
__device__ float g_sumsq[CC];

// ---------------- weight transposes ----------------------------------------
__global__ void k_wt1(const float* __restrict__ cw_w1, const float* __restrict__ dw_w1) {
    int idx = blockIdx.x*blockDim.x + threadIdx.x;
    if (idx >= IC1*9*OC1) return;
    int oc  = idx % OC1;
    int red = idx / OC1;           // ic*9 + r*3 + s
    int ic  = red / 9, rs = red % 9;
    const float* w = (oc < 64) ? cw_w1 : dw_w1;
    int o = (oc < 64) ? oc : oc - 64;
    g_w1t[idx] = w[(o*IC1 + ic)*9 + rs];
}

__global__ void k_wt2(const float* __restrict__ cw_w2) {
    int idx = blockIdx.x*blockDim.x + threadIdx.x;
    if (idx >= CC*9*OC2) return;
    int oc  = idx % OC2;
    int red = idx / OC2;
    int ic  = red / 9, rs = red % 9;
    g_w2t[idx] = cw_w2[(oc*CC + ic)*9 + rs];
}

// ---------------- conv1: both KGN first convs fused, 128 oc, relu ----------
// block: 512 thr = 16 warps; warp -> 8 oc; full 256-px row, 8 px/lane (4 pairs)
// FFMA2 path: weights duplicated in smem, input tile kept in two shift-copies
__global__ void __launch_bounds__(512, 1)
k_conv1(const float* __restrict__ input, const float* __restrict__ guidance,
        const float* __restrict__ cw_b1, const float* __restrict__ dw_b1) {
    extern __shared__ float sm[];
    float* tse = sm;                 // [8*3][260]  even-shift copy: tse[x] = row[x-1]
    float* tso = sm + 24*ROWL;       // [8*3][260]  odd-shift copy:  tso[x] = row[x]
    float* wsd = sm + 48*ROWL;       // [72][128*2] duplicated weights
    int tid = threadIdx.x, lane = tid & 31, warp = tid >> 5;
    int h = blockIdx.x;
    int b = blockIdx.y;
    int oc0 = warp * 8;

    ull acc[8][4];
    #pragma unroll
    for (int i = 0; i < 8; i++)
        #pragma unroll
        for (int jj = 0; jj < 4; jj++) acc[i][jj] = 0ULL;

    for (int icc = 0; icc < 16; icc++) {
        int ic0 = icc * 8;
        __syncthreads();
        // input tile fill (both shift copies from one gmem read)
        for (int i = tid; i < 24*ROWL; i += 512) {
            int x = i % ROWL;
            int t = i / ROWL;
            int r = t % 3;
            int ci = t / 3;
            int hh = h - 1 + r;
            int ww = x - 1;
            float v = 0.f;
            if (hh >= 0 && hh < HH && ww >= 0 && ww < WWI) {
                int ic = ic0 + ci;
                const float* src = (ic < 64) ? input : guidance;
                int icl = ic & 63;
                v = src[((b*64 + icl)*HH + hh)*WWI + ww];
            }
            tse[i] = v;
            if (x >= 1) tso[i - 1] = v;
        }
        // duplicated weights fill
        for (int i = tid; i < 72*128; i += 512) {
            float w = g_w1t[ic0*9*128 + i];
            wsd[2*i] = w; wsd[2*i + 1] = w;
        }
        __syncthreads();

        #pragma unroll 1
        for (int ci = 0; ci < 8; ci++) {
            #pragma unroll
            for (int r = 0; r < 3; r++) {
                int row = (ci*3 + r)*ROWL;
                #pragma unroll
                for (int s = 0; s < 3; s++) {
                    const float* tp = (s == 1) ? tso : tse;
                    int xo = (s == 1) ? 0 : s;
                    ull t2[4];
                    #pragma unroll
                    for (int jj = 0; jj < 4; jj++)
                        t2[jj] = *(const ull*)&tp[row + 2*lane + jj*64 + xo];
                    const ull* wp = (const ull*)&wsd[(ci*9 + r*3 + s)*256 + oc0*2];
                    #pragma unroll
                    for (int i = 0; i < 8; i++) {
                        ull w2 = wp[i];
                        #pragma unroll
                        for (int jj = 0; jj < 4; jj++) fma2(acc[i][jj], w2, t2[jj]);
                    }
                }
            }
        }
    }
    #pragma unroll
    for (int i = 0; i < 8; i++) {
        int oc = oc0 + i;
        float bias = (oc < 64) ? cw_b1[oc] : dw_b1[oc - 64];
        float* outp = &g_t[((b*OC1 + oc)*HH + h)*WWI];
        #pragma unroll
        for (int jj = 0; jj < 4; jj++) {
            float lo, hi; unpack2(acc[i][jj], lo, hi);
            int px = 2*lane + jj*64;
            *(float2*)&outp[px] = make_float2(fmaxf(lo + bias, 0.f), fmaxf(hi + bias, 0.f));
        }
    }
}

// ---------------- GAP of dw-branch conv ------------------------------------
__global__ void k_hmean() {
    int b = blockIdx.x >> 6;
    int c = blockIdx.x & 63;
    const float* p = &g_t[(b*OC1 + 64 + c)*HWN];
    float s = 0.f;
    for (int i = threadIdx.x; i < HWN; i += 256) s += p[i];
    __shared__ float red[256];
    red[threadIdx.x] = s; __syncthreads();
    for (int k = 128; k > 0; k >>= 1) {
        if (threadIdx.x < k) red[threadIdx.x] += red[threadIdx.x + k];
        __syncthreads();
    }
    if (threadIdx.x == 0) g_hmean[b*CC + c] = red[0] * (1.f/HWN);
}

// ---------------- depthwise-mixing 1x1 weights -----------------------------
__global__ void k_dw(const float* __restrict__ dw_w2, const float* __restrict__ dw_b2) {
    int idx = blockIdx.x*blockDim.x + threadIdx.x;  // (b*64 + o)*64 + c
    if (idx >= BB*CC*CC) return;
    int c = idx & 63;
    int o = (idx >> 6) & 63;
    int b = idx >> 12;
    float s = dw_b2[o*CC + c];
    const float* wrow = &dw_w2[(o*CC + c)*CC];
    const float* hm = &g_hmean[b*CC];
    #pragma unroll 8
    for (int ic = 0; ic < CC; ic++) s += hm[ic]*wrow[ic];
    g_dwT[(b*CC + c)*CC + o] = s;
}

// ---------------- fused conv2 (64->576) + guided depthwise combine ---------
// block: 512 thr = 16 warps; warp -> 1 c (9 cw taps); full 256-px row, 8 px/lane
__global__ void __launch_bounds__(512, 1)
k_conv2g(const float* __restrict__ input, const float* __restrict__ cw_b2) {
    extern __shared__ float sm[];
    float* tse = sm;                 // [24][260]
    float* tso = sm + 24*ROWL;       // [24][260]
    float* wsd = sm + 48*ROWL;       // [72][144*2] duplicated weights
    int tid = threadIdx.x, lane = tid & 31, warp = tid >> 5;
    int h  = blockIdx.x;
    int b  = blockIdx.y >> 2;
    int c0 = (blockIdx.y & 3) * 16;
    int c  = c0 + warp;

    ull acc[9][4];
    #pragma unroll
    for (int k = 0; k < 9; k++) {
        float bk = cw_b2[c*9 + k];
        ull p = pack2(bk, bk);
        #pragma unroll
        for (int jj = 0; jj < 4; jj++) acc[k][jj] = p;
    }

    for (int icc = 0; icc < 8; icc++) {
        int ic0 = icc * 8;
        __syncthreads();
        for (int i = tid; i < 24*ROWL; i += 512) {
            int x = i % ROWL;
            int t = i / ROWL;
            int r = t % 3;
            int ci = t / 3;
            int hh = h - 1 + r;
            int ww = x - 1;
            float v = 0.f;
            if (hh >= 0 && hh < HH && ww >= 0 && ww < WWI)
                v = g_t[((b*OC1 + ic0 + ci)*HH + hh)*WWI + ww];
            tse[i] = v;
            if (x >= 1) tso[i - 1] = v;
        }
        for (int i = tid; i < 72*144; i += 512) {
            int rr = i / 144, rem = i % 144;
            float w = g_w2t[(ic0*9 + rr)*OC2 + c0*9 + rem];
            wsd[rr*288 + 2*rem] = w; wsd[rr*288 + 2*rem + 1] = w;
        }
        __syncthreads();

        #pragma unroll 1
        for (int ci = 0; ci < 8; ci++) {
            #pragma unroll
            for (int r = 0; r < 3; r++) {
                int row = (ci*3 + r)*ROWL;
                #pragma unroll
                for (int s = 0; s < 3; s++) {
                    const float* tp = (s == 1) ? tso : tse;
                    int xo = (s == 1) ? 0 : s;
                    ull t2[4];
                    #pragma unroll
                    for (int jj = 0; jj < 4; jj++)
                        t2[jj] = *(const ull*)&tp[row + 2*lane + jj*64 + xo];
                    const ull* wp = (const ull*)&wsd[(ci*9 + r*3 + s)*288 + warp*18];
                    #pragma unroll
                    for (int k = 0; k < 9; k++) {
                        ull w2 = wp[k];
                        #pragma unroll
                        for (int jj = 0; jj < 4; jj++) fma2(acc[k][jj], w2, t2[jj]);
                    }
                }
            }
        }
    }
    // combine with 3x3 input patches (patch k = kh*3+kw, cw channel 9c+k)
    #pragma unroll
    for (int jj = 0; jj < 4; jj++) {
        int px = 2*lane + jj*64;
        float cw0[9], cw1[9];
        #pragma unroll
        for (int k = 0; k < 9; k++) unpack2(acc[k][jj], cw0[k], cw1[k]);
        float y0 = 0.f, y1 = 0.f;
        #pragma unroll
        for (int kh = 0; kh < 3; kh++) {
            int hh = h - 1 + kh;
            if (hh < 0 || hh >= HH) continue;
            const float* rowp = &input[((b*CC + c)*HH + hh)*WWI];
            float pm1 = (px > 0) ? rowp[px - 1] : 0.f;
            float p0  = rowp[px];
            float p1  = rowp[px + 1];
            float p2  = (px + 2 < WWI) ? rowp[px + 2] : 0.f;
            y0 += cw0[kh*3+0]*pm1 + cw0[kh*3+1]*p0 + cw0[kh*3+2]*p1;
            y1 += cw1[kh*3+0]*p0  + cw1[kh*3+1]*p1 + cw1[kh*3+2]*p2;
        }
        *(float2*)&g_y[((b*CC + c)*HH + h)*WWI + px] = make_float2(y0, y1);
    }
}

// ---------------- per-sample 1x1 (einsum) ----------------------------------
__global__ void k_einsum() {
    extern __shared__ float sm[];
    float* sy  = sm;              // [64][256]
    float* sdw = sm + 64*256;     // [c][o] 64x64
    int tid = threadIdx.x;        // 256
    int h = blockIdx.x & 255;
    int b = blockIdx.x >> 8;
    for (int c = 0; c < 64; c++)
        sy[c*256 + tid] = g_y[(b*CC + c)*HWN + h*WWI + tid];
    for (int i = tid; i < 4096; i += 256)
        sdw[i] = g_dwT[b*4096 + i];
    __syncthreads();

    float accz[64];
    #pragma unroll
    for (int o = 0; o < 64; o++) accz[o] = 0.f;
    #pragma unroll 4
    for (int c = 0; c < 64; c++) {
        float yv = sy[c*256 + tid];
        const float4* dp = (const float4*)&sdw[c*64];
        #pragma unroll
        for (int o4 = 0; o4 < 16; o4++) {
            float4 d = dp[o4];
            accz[o4*4+0] += yv*d.x;
            accz[o4*4+1] += yv*d.y;
            accz[o4*4+2] += yv*d.z;
            accz[o4*4+3] += yv*d.w;
        }
    }
    #pragma unroll
    for (int o = 0; o < 64; o++)
        g_z[(b*CC + o)*HWN + h*WWI + tid] = accz[o];
}

// ---------------- BN stats ---------------------------------------------------
__global__ void k_zero() {
    int i = threadIdx.x;
    if (i < CC) { g_sum[i] = 0.f; g_sumsq[i] = 0.f; }
}

__global__ void k_stats() {
    int o = blockIdx.x >> 2, part = blockIdx.x & 3;  // 4 blocks per channel
    float s = 0.f, s2 = 0.f;
    for (int b = 0; b < BB; b++) {
        const float* p = &g_z[(b*CC + o)*HWN + part*16384];
        for (int i = threadIdx.x; i < 16384; i += 256) {
            float v = p[i]; s += v; s2 += v*v;
        }
    }
    __shared__ float r1[256], r2[256];
    r1[threadIdx.x] = s; r2[threadIdx.x] = s2; __syncthreads();
    for (int k = 128; k > 0; k >>= 1) {
        if (threadIdx.x < k) { r1[threadIdx.x] += r1[threadIdx.x + k]; r2[threadIdx.x] += r2[threadIdx.x + k]; }
        __syncthreads();
    }
    if (threadIdx.x == 0) { atomicAdd(&g_sum[o], r1[0]); atomicAdd(&g_sumsq[o], r2[0]); }
}

// ---------------- BN normalize + relu ---------------------------------------
__global__ void k_bn(const float* __restrict__ gamma, const float* __restrict__ beta,
                     float* __restrict__ out) {
    const float invN = 1.f/(float)(BB*HWN);
    int idx = blockIdx.x*blockDim.x + threadIdx.x;
    int stride = gridDim.x*blockDim.x;
    int total4 = BB*CC*HWN/4;
    const float4* zp = (const float4*)g_z;
    float4* op = (float4*)out;
    for (int i = idx; i < total4; i += stride) {
        int o = (i >> 14) & 63;
        float mu  = g_sum[o]*invN;
        float var = g_sumsq[o]*invN - mu*mu;
        float rs  = rsqrtf(var + EPSF);
        float ga = gamma[o]*rs, be = beta[o];
        float4 z = zp[i];
        float4 r;
        r.x = fmaxf((z.x - mu)*ga + be, 0.f);
        r.y = fmaxf((z.y - mu)*ga + be, 0.f);
        r.z = fmaxf((z.z - mu)*ga + be, 0.f);
        r.w = fmaxf((z.w - mu)*ga + be, 0.f);
        op[i] = r;
    }
}

// ---------------- launch -----------------------------------------------------
extern "C" void kernel_launch(void* const* d_in, const int* in_sizes, int n_in,
                              void* d_out, int out_size) {
    const float* input    = (const float*)d_in[0];
    const float* guidance = (const float*)d_in[1];
    const float* cw_w1    = (const float*)d_in[2];
    const float* cw_b1    = (const float*)d_in[3];
    const float* cw_w2    = (const float*)d_in[4];
    const float* cw_b2    = (const float*)d_in[5];
    const float* dw_w1    = (const float*)d_in[6];
    const float* dw_b1    = (const float*)d_in[7];
    const float* dw_w2    = (const float*)d_in[8];
    const float* dw_b2    = (const float*)d_in[9];
    const float* bn_gamma = (const float*)d_in[10];
    const float* bn_beta  = (const float*)d_in[11];
    float* out = (float*)d_out;

    const int smem1 = (48*ROWL + 72*256)*4;   // 123648 B
    const int smem2 = (48*ROWL + 72*288)*4;   // 132864 B
    cudaFuncSetAttribute(k_conv1,  cudaFuncAttributeMaxDynamicSharedMemorySize, smem1);
    cudaFuncSetAttribute(k_conv2g, cudaFuncAttributeMaxDynamicSharedMemorySize, smem2);
    cudaFuncSetAttribute(k_einsum, cudaFuncAttributeMaxDynamicSharedMemorySize, (64*256 + 64*64)*4);

    k_wt1<<<(IC1*9*OC1 + 255)/256, 256>>>(cw_w1, dw_w1);
    k_wt2<<<(CC*9*OC2 + 255)/256, 256>>>(cw_w2);
    k_conv1<<<dim3(256, 2), 512, smem1>>>(input, guidance, cw_b1, dw_b1);
    k_hmean<<<128, 256>>>();
    k_dw<<<(BB*CC*CC + 255)/256, 256>>>(dw_w2, dw_b2);
    k_conv2g<<<dim3(256, 8), 512, smem2>>>(input, cw_b2);
    k_einsum<<<512, 256, (64*256 + 64*64)*4>>>();
    k_zero<<<1, 64>>>();
    k_stats<<<256, 256>>>();
    k_bn<<<1024, 256>>>(bn_gamma, bn_beta, out);
}

// round 3
// speedup vs baseline: 7.5705x; 7.5705x over previous
#include <cuda_runtime.h>
#include <cuda_fp16.h>

typedef unsigned int uint;

#define BB   2
#define HH   256
#define WWI  256
#define HWN  65536
#define EPSF 1e-5f

// ---------------- scratch (static device globals) ---------------------------
__device__ __half g_w1h[9*8*128*16];      // [tap][cc][oc128][ic16]
__device__ __half g_w2h[9*4*576*16];      // [tap][cc][oc576][ic16]
__device__ __half g_xt[BB*HH*WWI*128];    // [b][h][x][ic128] (input||guidance)
__device__ __half g_tt[BB*HH*WWI*64];     // conv1 cw-branch out  [b][h][x][ic64]
__device__ float  g_t2[BB*64*HWN];        // conv1 dw-branch out  [b][oc][h][x]
__device__ float  g_y[BB*64*HWN];
__device__ float  g_z[BB*64*HWN];
__device__ float  g_hmean[BB*64];
__device__ float  g_dwT[BB*64*64];        // [b][c][o]
__device__ float  g_sum[64];
__device__ float  g_sumsq[64];

// ---------------- mma helper -------------------------------------------------
__device__ __forceinline__ void mma16816(float* d, const uint* a, uint b0, uint b1) {
    asm volatile("mma.sync.aligned.m16n8k16.row.col.f32.f16.f16.f32 "
        "{%0,%1,%2,%3}, {%4,%5,%6,%7}, {%8,%9}, {%0,%1,%2,%3};"
        : "+f"(d[0]), "+f"(d[1]), "+f"(d[2]), "+f"(d[3])
        : "r"(a[0]), "r"(a[1]), "r"(a[2]), "r"(a[3]), "r"(b0), "r"(b1));
}

// ---------------- weight packing to fp16 ------------------------------------
__global__ void k_wt1h(const float* __restrict__ cw_w1, const float* __restrict__ dw_w1) {
    int idx = blockIdx.x*blockDim.x + threadIdx.x;
    if (idx >= 9*8*128*16) return;
    int ici = idx & 15;
    int oc  = (idx >> 4) & 127;
    int cc  = (idx >> 11) & 7;
    int tap = idx >> 14;
    int ic = cc*16 + ici;
    float v = (oc < 64) ? cw_w1[(oc*128 + ic)*9 + tap]
                        : dw_w1[((oc-64)*128 + ic)*9 + tap];
    g_w1h[idx] = __float2half_rn(v);
}

__global__ void k_wt2h(const float* __restrict__ cw_w2) {
    int idx = blockIdx.x*blockDim.x + threadIdx.x;
    if (idx >= 9*4*576*16) return;
    int ici = idx & 15;
    int oc  = (idx >> 4) % 576;
    int rest = idx / (16*576);
    int cc  = rest & 3;
    int tap = rest >> 2;
    g_w2h[idx] = __float2half_rn(cw_w2[(oc*64 + cc*16 + ici)*9 + tap]);
}

// ---------------- activation transpose to [b][h][x][ic] fp16 ----------------
__global__ void k_xt(const float* __restrict__ input, const float* __restrict__ guidance) {
    __shared__ __half st[32*136];
    int tid = threadIdx.x;
    int x0 = blockIdx.x * 32;
    int h  = blockIdx.y;
    int b  = blockIdx.z;
    int xl = tid & 31;
    int icr = tid >> 5;           // 0..7
    #pragma unroll
    for (int p = 0; p < 16; p++) {
        int ic = p*8 + icr;
        const float* src = (ic < 64) ? input : guidance;
        int icl = ic & 63;
        float v = src[((b*64 + icl)*HH + h)*WWI + x0 + xl];
        st[xl*136 + ic] = __float2half_rn(v);
    }
    __syncthreads();
    uint* dst = (uint*)g_xt;
    const uint* sp = (const uint*)st;
    #pragma unroll
    for (int it = 0; it < 8; it++) {
        int i = it*256 + tid;
        int u  = i & 63;
        int xr = i >> 6;
        dst[((((b*HH + h)*WWI) + x0 + xr) << 6) + u] = sp[xr*68 + u];
    }
}

// ---------------- conv1: tensor-core implicit GEMM --------------------------
// block 256 thr = 8 warps (4 m-warps x 2 n-warps); tile: oc128 x 64px, K=1152
__global__ void __launch_bounds__(256) k_conv1(const float* __restrict__ cw_b1,
                                               const float* __restrict__ dw_b1) {
    extern __shared__ __half sB[];         // [3][66][136]
    int tid = threadIdx.x, lane = tid & 31, w = tid >> 5;
    int x0 = blockIdx.x * 64;
    int h  = blockIdx.y;
    int b  = blockIdx.z;

    // stage B tile (3 rows x 66 cols x 128 ic halves) from g_xt
    {
        uint* sBu = (uint*)sB;
        const uint* xt = (const uint*)g_xt;
        for (int i = tid; i < 3*66*64; i += 256) {
            int u = i & 63;
            int rest = i >> 6;
            int xi = rest % 66;
            int r  = rest / 66;
            int hh = h - 1 + r, xx = x0 - 1 + xi;
            uint v = 0;
            if (hh >= 0 && hh < HH && xx >= 0 && xx < WWI)
                v = xt[((((b*HH + hh)*WWI) + xx) << 6) + u];
            sBu[(r*66 + xi)*68 + u] = v;
        }
    }
    __syncthreads();

    int g = lane >> 2, t = lane & 3;
    int m0 = (w & 3) * 32;
    int n0 = (w >> 2) * 32;

    float acc[2][4][4];
    #pragma unroll
    for (int mt = 0; mt < 2; mt++)
        #pragma unroll
        for (int nt = 0; nt < 4; nt++)
            #pragma unroll
            for (int q = 0; q < 4; q++) acc[mt][nt][q] = 0.f;

    for (int tap = 0; tap < 9; tap++) {
        int r = tap / 3;
        int s = tap - r*3;
        #pragma unroll
        for (int cc = 0; cc < 8; cc++) {
            int kc = cc * 16;
            uint a[2][4];
            #pragma unroll
            for (int mt = 0; mt < 2; mt++) {
                const uint* p = (const uint*)(g_w1h + (((tap*8 + cc)*128 + m0 + mt*16 + g) << 4) + 2*t);
                a[mt][0] = p[0];
                a[mt][1] = p[64];   // +8 rows (8*16 halves)
                a[mt][2] = p[4];    // +8 k
                a[mt][3] = p[68];
            }
            #pragma unroll
            for (int nt = 0; nt < 4; nt++) {
                const uint* p = (const uint*)(sB + (r*66 + n0 + nt*8 + g + s)*136 + kc + 2*t);
                uint b0 = p[0], b1 = p[4];
                mma16816(acc[0][nt], a[0], b0, b1);
                mma16816(acc[1][nt], a[1], b0, b1);
            }
        }
    }

    // epilogue: bias + relu; t1 (oc<64) -> g_tt fp16, t2 -> g_t2 fp32
    #pragma unroll
    for (int mt = 0; mt < 2; mt++) {
        int ocb = m0 + mt*16;
        if (ocb < 64) {
            int oc0 = ocb + g, oc1 = ocb + 8 + g;
            float bv0 = cw_b1[oc0], bv1 = cw_b1[oc1];
            #pragma unroll
            for (int nt = 0; nt < 4; nt++) {
                int x = x0 + n0 + nt*8 + 2*t;
                size_t base = ((size_t)((b*HH + h)*WWI + x)) << 6;
                g_tt[base + oc0]      = __float2half_rn(fmaxf(acc[mt][nt][0] + bv0, 0.f));
                g_tt[base + 64 + oc0] = __float2half_rn(fmaxf(acc[mt][nt][1] + bv0, 0.f));
                g_tt[base + oc1]      = __float2half_rn(fmaxf(acc[mt][nt][2] + bv1, 0.f));
                g_tt[base + 64 + oc1] = __float2half_rn(fmaxf(acc[mt][nt][3] + bv1, 0.f));
            }
        } else {
            int oc0 = ocb - 64 + g, oc1 = oc0 + 8;
            float bv0 = dw_b1[oc0], bv1 = dw_b1[oc1];
            #pragma unroll
            for (int nt = 0; nt < 4; nt++) {
                int x = x0 + n0 + nt*8 + 2*t;
                float2 v0 = make_float2(fmaxf(acc[mt][nt][0] + bv0, 0.f),
                                        fmaxf(acc[mt][nt][1] + bv0, 0.f));
                float2 v1 = make_float2(fmaxf(acc[mt][nt][2] + bv1, 0.f),
                                        fmaxf(acc[mt][nt][3] + bv1, 0.f));
                *(float2*)&g_t2[((b*64 + oc0)*HH + h)*WWI + x] = v0;
                *(float2*)&g_t2[((b*64 + oc1)*HH + h)*WWI + x] = v1;
            }
        }
    }
}

// ---------------- GAP of dw-branch ------------------------------------------
__global__ void k_hmean() {
    int b = blockIdx.x >> 6;
    int c = blockIdx.x & 63;
    const float* p = &g_t2[(b*64 + c)*HWN];
    float s = 0.f;
    for (int i = threadIdx.x; i < HWN; i += 256) s += p[i];
    __shared__ float red[256];
    red[threadIdx.x] = s; __syncthreads();
    for (int k = 128; k > 0; k >>= 1) {
        if (threadIdx.x < k) red[threadIdx.x] += red[threadIdx.x + k];
        __syncthreads();
    }
    if (threadIdx.x == 0) g_hmean[b*64 + c] = red[0] * (1.f/HWN);
}

// ---------------- depthwise-mixing 1x1 weights ------------------------------
__global__ void k_dw(const float* __restrict__ dw_w2, const float* __restrict__ dw_b2) {
    int idx = blockIdx.x*blockDim.x + threadIdx.x;
    if (idx >= BB*64*64) return;
    int c = idx & 63;
    int o = (idx >> 6) & 63;
    int b = idx >> 12;
    float s = dw_b2[o*64 + c];
    const float* wrow = &dw_w2[(o*64 + c)*64];
    const float* hm = &g_hmean[b*64];
    #pragma unroll 8
    for (int ic = 0; ic < 64; ic++) s += hm[ic]*wrow[ic];
    g_dwT[(b*64 + c)*64 + o] = s;
}

// ---------------- conv2 tensor GEMM + guided combine ------------------------
// block 384 thr = 12 warps, each m48 x n64; C tile 576 x 64, K = 576
__device__ __forceinline__ void c2_loadA(int ch, int m0, int g, int t, uint a[3][4]) {
    int tap = ch >> 2, cc = ch & 3;
    #pragma unroll
    for (int mt = 0; mt < 3; mt++) {
        const uint* p = (const uint*)(g_w2h + (((tap*4 + cc)*576 + m0 + mt*16 + g) << 4) + 2*t);
        a[mt][0] = p[0];
        a[mt][1] = p[64];
        a[mt][2] = p[4];
        a[mt][3] = p[68];
    }
}

__device__ __forceinline__ void c2_step(int ch, const __half* sB, int g, int t,
                                        const uint a[3][4], float acc[3][8][4]) {
    int tap = ch >> 2, cc = ch & 3;
    int r = tap / 3;
    int s = tap - r*3;
    int kc = cc * 16;
    #pragma unroll
    for (int nt = 0; nt < 8; nt++) {
        const uint* p = (const uint*)(sB + (r*66 + nt*8 + g + s)*72 + kc + 2*t);
        uint b0 = p[0], b1 = p[4];
        mma16816(acc[0][nt], a[0], b0, b1);
        mma16816(acc[1][nt], a[1], b0, b1);
        mma16816(acc[2][nt], a[2], b0, b1);
    }
}

__global__ void __launch_bounds__(384, 1) k_conv2g(const float* __restrict__ input,
                                                   const float* __restrict__ cw_b2) {
    extern __shared__ float smf[];
    float* scw = smf;                                // [576][65]
    __half* sB = (__half*)(smf + 576*65);            // [3][66][72]
    int tid = threadIdx.x, lane = tid & 31, w = tid >> 5;
    int x0 = blockIdx.x * 64;
    int h  = blockIdx.y;
    int b  = blockIdx.z;

    // stage B tile from g_tt
    {
        uint* sBu = (uint*)sB;
        const uint* tt = (const uint*)g_tt;
        for (int i = tid; i < 3*66*32; i += 384) {
            int u = i & 31;
            int rest = i >> 5;
            int xi = rest % 66;
            int r  = rest / 66;
            int hh = h - 1 + r, xx = x0 - 1 + xi;
            uint v = 0;
            if (hh >= 0 && hh < HH && xx >= 0 && xx < WWI)
                v = tt[((((b*HH + hh)*WWI) + xx) << 5) + u];
            sBu[(r*66 + xi)*36 + u] = v;
        }
    }
    __syncthreads();

    int g = lane >> 2, t = lane & 3;
    int m0 = w * 48;

    float acc[3][8][4];
    #pragma unroll
    for (int mt = 0; mt < 3; mt++)
        #pragma unroll
        for (int nt = 0; nt < 8; nt++)
            #pragma unroll
            for (int q = 0; q < 4; q++) acc[mt][nt][q] = 0.f;

    uint aA[3][4], aB[3][4];
    c2_loadA(0, m0, g, t, aA);
    for (int ch2 = 0; ch2 < 18; ch2++) {
        int ch = ch2*2;
        c2_loadA(ch + 1, m0, g, t, aB);
        c2_step(ch, sB, g, t, aA, acc);
        if (ch + 2 < 36) c2_loadA(ch + 2, m0, g, t, aA);
        c2_step(ch + 1, sB, g, t, aB, acc);
    }

    // store C tile (+bias) to smem slab
    #pragma unroll
    for (int mt = 0; mt < 3; mt++) {
        int oc0 = m0 + mt*16 + g, oc1 = oc0 + 8;
        float bv0 = cw_b2[oc0], bv1 = cw_b2[oc1];
        #pragma unroll
        for (int nt = 0; nt < 8; nt++) {
            int x = nt*8 + 2*t;
            scw[oc0*65 + x]     = acc[mt][nt][0] + bv0;
            scw[oc0*65 + x + 1] = acc[mt][nt][1] + bv0;
            scw[oc1*65 + x]     = acc[mt][nt][2] + bv1;
            scw[oc1*65 + x + 1] = acc[mt][nt][3] + bv1;
        }
    }
    __syncthreads();

    // guided combine: y[c][x] = sum_k cw[9c+k][x] * input_patch
    for (int idx = tid; idx < 4096; idx += 384) {
        int c = idx >> 6, x = idx & 63;
        int gx = x0 + x;
        float y = 0.f;
        #pragma unroll
        for (int kh = 0; kh < 3; kh++) {
            int hh = h - 1 + kh;
            if (hh < 0 || hh >= HH) continue;
            const float* rowp = input + ((b*64 + c)*HH + hh)*WWI;
            #pragma unroll
            for (int kw = 0; kw < 3; kw++) {
                int ww = gx - 1 + kw;
                if (ww < 0 || ww >= WWI) continue;
                y += scw[(9*c + kh*3 + kw)*65 + x] * rowp[ww];
            }
        }
        g_y[(b*64 + c)*HWN + h*WWI + gx] = y;
    }
}

// ---------------- per-sample 1x1 (einsum) -----------------------------------
__global__ void k_einsum() {
    extern __shared__ float sm[];
    float* sy  = sm;              // [64][256]
    float* sdw = sm + 64*256;     // [c][o]
    int tid = threadIdx.x;        // 256
    int h = blockIdx.x & 255;
    int b = blockIdx.x >> 8;
    for (int c = 0; c < 64; c++)
        sy[c*256 + tid] = g_y[(b*64 + c)*HWN + h*WWI + tid];
    for (int i = tid; i < 4096; i += 256)
        sdw[i] = g_dwT[b*4096 + i];
    __syncthreads();

    float accz[64];
    #pragma unroll
    for (int o = 0; o < 64; o++) accz[o] = 0.f;
    #pragma unroll 4
    for (int c = 0; c < 64; c++) {
        float yv = sy[c*256 + tid];
        const float4* dp = (const float4*)&sdw[c*64];
        #pragma unroll
        for (int o4 = 0; o4 < 16; o4++) {
            float4 d = dp[o4];
            accz[o4*4+0] += yv*d.x;
            accz[o4*4+1] += yv*d.y;
            accz[o4*4+2] += yv*d.z;
            accz[o4*4+3] += yv*d.w;
        }
    }
    #pragma unroll
    for (int o = 0; o < 64; o++)
        g_z[(b*64 + o)*HWN + h*WWI + tid] = accz[o];
}

// ---------------- BN ---------------------------------------------------------
__global__ void k_zero() {
    int i = threadIdx.x;
    if (i < 64) { g_sum[i] = 0.f; g_sumsq[i] = 0.f; }
}

__global__ void k_stats() {
    int o = blockIdx.x >> 2, part = blockIdx.x & 3;
    float s = 0.f, s2 = 0.f;
    for (int b = 0; b < BB; b++) {
        const float* p = &g_z[(b*64 + o)*HWN + part*16384];
        for (int i = threadIdx.x; i < 16384; i += 256) {
            float v = p[i]; s += v; s2 += v*v;
        }
    }
    __shared__ float r1[256], r2[256];
    r1[threadIdx.x] = s; r2[threadIdx.x] = s2; __syncthreads();
    for (int k = 128; k > 0; k >>= 1) {
        if (threadIdx.x < k) { r1[threadIdx.x] += r1[threadIdx.x + k]; r2[threadIdx.x] += r2[threadIdx.x + k]; }
        __syncthreads();
    }
    if (threadIdx.x == 0) { atomicAdd(&g_sum[o], r1[0]); atomicAdd(&g_sumsq[o], r2[0]); }
}

__global__ void k_bn(const float* __restrict__ gamma, const float* __restrict__ beta,
                     float* __restrict__ out) {
    const float invN = 1.f/(float)(BB*HWN);
    int idx = blockIdx.x*blockDim.x + threadIdx.x;
    int stride = gridDim.x*blockDim.x;
    int total4 = BB*64*HWN/4;
    const float4* zp = (const float4*)g_z;
    float4* op = (float4*)out;
    for (int i = idx; i < total4; i += stride) {
        int o = (i >> 14) & 63;
        float mu  = g_sum[o]*invN;
        float var = g_sumsq[o]*invN - mu*mu;
        float rs  = rsqrtf(var + EPSF);
        float ga = gamma[o]*rs, be = beta[o];
        float4 z = zp[i];
        float4 r;
        r.x = fmaxf((z.x - mu)*ga + be, 0.f);
        r.y = fmaxf((z.y - mu)*ga + be, 0.f);
        r.z = fmaxf((z.z - mu)*ga + be, 0.f);
        r.w = fmaxf((z.w - mu)*ga + be, 0.f);
        op[i] = r;
    }
}

// ---------------- launch -----------------------------------------------------
extern "C" void kernel_launch(void* const* d_in, const int* in_sizes, int n_in,
                              void* d_out, int out_size) {
    const float* input    = (const float*)d_in[0];
    const float* guidance = (const float*)d_in[1];
    const float* cw_w1    = (const float*)d_in[2];
    const float* cw_b1    = (const float*)d_in[3];
    const float* cw_w2    = (const float*)d_in[4];
    const float* cw_b2    = (const float*)d_in[5];
    const float* dw_w1    = (const float*)d_in[6];
    const float* dw_b1    = (const float*)d_in[7];
    const float* dw_w2    = (const float*)d_in[8];
    const float* dw_b2    = (const float*)d_in[9];
    const float* bn_gamma = (const float*)d_in[10];
    const float* bn_beta  = (const float*)d_in[11];
    float* out = (float*)d_out;

    const int smem1 = 3*66*136*2;                    // 53856
    const int smem2 = 576*65*4 + 3*66*72*2;          // 178272
    cudaFuncSetAttribute(k_conv1,  cudaFuncAttributeMaxDynamicSharedMemorySize, smem1);
    cudaFuncSetAttribute(k_conv2g, cudaFuncAttributeMaxDynamicSharedMemorySize, smem2);
    cudaFuncSetAttribute(k_einsum, cudaFuncAttributeMaxDynamicSharedMemorySize, (64*256 + 64*64)*4);

    k_wt1h<<<(9*8*128*16 + 255)/256, 256>>>(cw_w1, dw_w1);
    k_wt2h<<<(9*4*576*16 + 255)/256, 256>>>(cw_w2);
    k_xt<<<dim3(8, 256, 2), 256>>>(input, guidance);
    k_conv1<<<dim3(4, 256, 2), 256, smem1>>>(cw_b1, dw_b1);
    k_hmean<<<128, 256>>>();
    k_dw<<<(BB*64*64 + 255)/256, 256>>>(dw_w2, dw_b2);
    k_conv2g<<<dim3(4, 256, 2), 384, smem2>>>(input, cw_b2);
    k_einsum<<<512, 256, (64*256 + 64*64)*4>>>();
    k_zero<<<1, 64>>>();
    k_stats<<<256, 256>>>();
    k_bn<<<1024, 256>>>(bn_gamma, bn_beta, out);
}

// round 4
// speedup vs baseline: 8.4832x; 1.1206x over previous
#include <cuda_runtime.h>
#include <cuda_fp16.h>

typedef unsigned int uint;

#define BB   2
#define HH   256
#define WWI  256
#define HWN  65536
#define EPSF 1e-5f

// ---------------- scratch (static device globals) ---------------------------
__device__ uint4  g_w1p[9*8*8*32];        // conv1 A fragments [tap][cc][mt16][lane]
__device__ uint4  g_w2p[9*4*36*32];       // conv2 A fragments [tap][cc][mt16][lane]
__device__ __half g_xt[BB*HH*WWI*128];    // [b][h][x][ic128] (input||guidance)
__device__ __half g_tt[BB*HH*WWI*64];     // conv1 cw-branch out [b][h][x][ic64]
__device__ float  g_y[BB*64*HWN];
__device__ float  g_z[BB*64*HWN];
__device__ float  g_hsum[BB*64];          // GAP partial sums (atomic)
__device__ float  g_dwT[BB*64*64];        // [b][c][o]
__device__ float  g_sum[64];
__device__ float  g_sumsq[64];

// ---------------- helpers ----------------------------------------------------
__device__ __forceinline__ void mma16816(float* d, const uint* a, uint b0, uint b1) {
    asm volatile("mma.sync.aligned.m16n8k16.row.col.f32.f16.f16.f32 "
        "{%0,%1,%2,%3}, {%4,%5,%6,%7}, {%8,%9}, {%0,%1,%2,%3};"
        : "+f"(d[0]), "+f"(d[1]), "+f"(d[2]), "+f"(d[3])
        : "r"(a[0]), "r"(a[1]), "r"(a[2]), "r"(a[3]), "r"(b0), "r"(b1));
}
__device__ __forceinline__ void ldsm4(uint& r0, uint& r1, uint& r2, uint& r3, uint addr) {
    asm volatile("ldmatrix.sync.aligned.m8n8.x4.shared.b16 {%0,%1,%2,%3}, [%4];"
        : "=r"(r0), "=r"(r1), "=r"(r2), "=r"(r3) : "r"(addr));
}
__device__ __forceinline__ uint ph2(float lo, float hi) {
    __half2 h = __floats2half2_rn(lo, hi);
    return *(uint*)&h;
}

// ---------------- weight fragment packing -----------------------------------
__device__ __forceinline__ float w1f(const float* cw, const float* dw, int oc, int ic, int tap) {
    return (oc < 64) ? cw[(oc*128 + ic)*9 + tap] : dw[((oc-64)*128 + ic)*9 + tap];
}
__global__ void k_wp1(const float* __restrict__ cw_w1, const float* __restrict__ dw_w1) {
    int idx = blockIdx.x*blockDim.x + threadIdx.x;
    if (idx >= 9*8*8*32) return;
    int lane = idx & 31, mt16 = (idx>>5)&7, cc = (idx>>8)&7, tap = idx>>11;
    int g = lane>>2, t = lane&3;
    int r0 = mt16*16+g, r1 = r0+8;
    int ic0 = cc*16 + 2*t, ic1 = ic0+8;
    uint4 v;
    v.x = ph2(w1f(cw_w1,dw_w1,r0,ic0,tap),  w1f(cw_w1,dw_w1,r0,ic0+1,tap));
    v.y = ph2(w1f(cw_w1,dw_w1,r1,ic0,tap),  w1f(cw_w1,dw_w1,r1,ic0+1,tap));
    v.z = ph2(w1f(cw_w1,dw_w1,r0,ic1,tap),  w1f(cw_w1,dw_w1,r0,ic1+1,tap));
    v.w = ph2(w1f(cw_w1,dw_w1,r1,ic1,tap),  w1f(cw_w1,dw_w1,r1,ic1+1,tap));
    g_w1p[idx] = v;
}
__global__ void k_wp2(const float* __restrict__ cw_w2) {
    int idx = blockIdx.x*blockDim.x + threadIdx.x;
    if (idx >= 9*4*36*32) return;
    int lane = idx & 31;
    int mt16 = (idx>>5) % 36;
    int rest = idx / (32*36);
    int cc = rest & 3, tap = rest >> 2;
    int g = lane>>2, t = lane&3;
    int r0 = mt16*16+g, r1 = r0+8;
    int ic0 = cc*16 + 2*t, ic1 = ic0+8;
    uint4 v;
    v.x = ph2(cw_w2[(r0*64+ic0)*9+tap],   cw_w2[(r0*64+ic0+1)*9+tap]);
    v.y = ph2(cw_w2[(r1*64+ic0)*9+tap],   cw_w2[(r1*64+ic0+1)*9+tap]);
    v.z = ph2(cw_w2[(r0*64+ic1)*9+tap],   cw_w2[(r0*64+ic1+1)*9+tap]);
    v.w = ph2(cw_w2[(r1*64+ic1)*9+tap],   cw_w2[(r1*64+ic1+1)*9+tap]);
    g_w2p[idx] = v;
}

// ---------------- activation transpose to [b][h][x][ic] fp16 ----------------
__global__ void k_xt(const float* __restrict__ input, const float* __restrict__ guidance) {
    __shared__ __half st[32*136];
    int tid = threadIdx.x;
    int x0 = blockIdx.x * 32;
    int h  = blockIdx.y;
    int b  = blockIdx.z;
    int xl = tid & 31;
    int icr = tid >> 5;
    #pragma unroll
    for (int p = 0; p < 16; p++) {
        int ic = p*8 + icr;
        const float* src = (ic < 64) ? input : guidance;
        int icl = ic & 63;
        float v = src[((b*64 + icl)*HH + h)*WWI + x0 + xl];
        st[xl*136 + ic] = __float2half_rn(v);
    }
    __syncthreads();
    uint* dst = (uint*)g_xt;
    const uint* sp = (const uint*)st;
    #pragma unroll
    for (int it = 0; it < 8; it++) {
        int i = it*256 + tid;
        int u  = i & 63;
        int xr = i >> 6;
        dst[((((b*HH + h)*WWI) + x0 + xr) << 6) + u] = sp[xr*68 + u];
    }
}

// ---------------- zero accumulators ------------------------------------------
__global__ void k_zero() {
    int i = threadIdx.x;
    if (i < 64)  { g_sum[i] = 0.f; g_sumsq[i] = 0.f; }
    if (i < 128) g_hsum[i] = 0.f;
}

// ---------------- conv1: tensor implicit GEMM + fused GAP -------------------
// 8 warps: mw=w&3 (32 oc each), nw=w>>2 (32 px each); tile oc128 x 64px, K=1152
__global__ void __launch_bounds__(256) k_conv1(const float* __restrict__ cw_b1,
                                               const float* __restrict__ dw_b1) {
    extern __shared__ __half sB[];         // [3][66][136]
    int tid = threadIdx.x, lane = tid & 31, w = tid >> 5;
    int x0 = blockIdx.x * 64;
    int h  = blockIdx.y;
    int b  = blockIdx.z;

    {   // stage B tile
        uint* sBu = (uint*)sB;
        const uint* xt = (const uint*)g_xt;
        for (int i = tid; i < 3*66*64; i += 256) {
            int u = i & 63;
            int rest = i >> 6;
            int xi = rest % 66;
            int r  = rest / 66;
            int hh = h - 1 + r, xx = x0 - 1 + xi;
            uint v = 0;
            if (hh >= 0 && hh < HH && xx >= 0 && xx < WWI)
                v = xt[((((b*HH + hh)*WWI) + xx) << 6) + u];
            sBu[(r*66 + xi)*68 + u] = v;
        }
    }
    __syncthreads();

    int g = lane >> 2, t = lane & 3;
    int mw = w & 3;
    int n0 = (w >> 2) * 32;
    uint sb32 = (uint)__cvta_generic_to_shared(sB);
    int row_off = (lane & 7) + ((lane & 16) ? 8 : 0);
    int col_off = (lane & 8) ? 8 : 0;

    float acc[2][4][4];
    #pragma unroll
    for (int mt = 0; mt < 2; mt++)
        #pragma unroll
        for (int nt = 0; nt < 4; nt++)
            #pragma unroll
            for (int q = 0; q < 4; q++) acc[mt][nt][q] = 0.f;

    for (int tap = 0; tap < 9; tap++) {
        int r = tap / 3;
        int s = tap - r*3;
        uint badd = sb32 + 2*(((r*66 + n0 + s + row_off)*136) + col_off);
        #pragma unroll
        for (int cc = 0; cc < 8; cc++) {
            int kc = cc*16;
            uint4 A0 = g_w1p[(((tap*8 + cc)*8) + mw*2 + 0)*32 + lane];
            uint4 A1 = g_w1p[(((tap*8 + cc)*8) + mw*2 + 1)*32 + lane];
            uint b0,b1,b2,b3, c0,c1,c2,c3;
            ldsm4(b0,b1,b2,b3, badd + 2*kc);
            ldsm4(c0,c1,c2,c3, badd + 2*(16*136 + kc));
            mma16816(acc[0][0], (const uint*)&A0, b0, b1);
            mma16816(acc[1][0], (const uint*)&A1, b0, b1);
            mma16816(acc[0][1], (const uint*)&A0, b2, b3);
            mma16816(acc[1][1], (const uint*)&A1, b2, b3);
            mma16816(acc[0][2], (const uint*)&A0, c0, c1);
            mma16816(acc[1][2], (const uint*)&A1, c0, c1);
            mma16816(acc[0][3], (const uint*)&A0, c2, c3);
            mma16816(acc[1][3], (const uint*)&A1, c2, c3);
        }
    }

    // epilogue
    #pragma unroll
    for (int mt = 0; mt < 2; mt++) {
        int ocb = mw*32 + mt*16;
        if (ocb < 64) {
            int oc0 = ocb + g, oc1 = ocb + 8 + g;
            float bv0 = cw_b1[oc0], bv1 = cw_b1[oc1];
            #pragma unroll
            for (int nt = 0; nt < 4; nt++) {
                int x = x0 + n0 + nt*8 + 2*t;
                size_t base = ((size_t)((b*HH + h)*WWI + x)) << 6;
                g_tt[base + oc0]      = __float2half_rn(fmaxf(acc[mt][nt][0] + bv0, 0.f));
                g_tt[base + 64 + oc0] = __float2half_rn(fmaxf(acc[mt][nt][1] + bv0, 0.f));
                g_tt[base + oc1]      = __float2half_rn(fmaxf(acc[mt][nt][2] + bv1, 0.f));
                g_tt[base + 64 + oc1] = __float2half_rn(fmaxf(acc[mt][nt][3] + bv1, 0.f));
            }
        } else {
            // dw branch: relu then global-average-pool partial (fused)
            int oc0 = ocb - 64 + g, oc1 = oc0 + 8;
            float bv0 = dw_b1[oc0], bv1 = dw_b1[oc1];
            float s0 = 0.f, s1 = 0.f;
            #pragma unroll
            for (int nt = 0; nt < 4; nt++) {
                s0 += fmaxf(acc[mt][nt][0] + bv0, 0.f) + fmaxf(acc[mt][nt][1] + bv0, 0.f);
                s1 += fmaxf(acc[mt][nt][2] + bv1, 0.f) + fmaxf(acc[mt][nt][3] + bv1, 0.f);
            }
            s0 += __shfl_xor_sync(0xffffffffu, s0, 1);
            s0 += __shfl_xor_sync(0xffffffffu, s0, 2);
            s1 += __shfl_xor_sync(0xffffffffu, s1, 1);
            s1 += __shfl_xor_sync(0xffffffffu, s1, 2);
            if (t == 0) {
                atomicAdd(&g_hsum[b*64 + oc0], s0);
                atomicAdd(&g_hsum[b*64 + oc1], s1);
            }
        }
    }
}

// ---------------- depthwise-mixing 1x1 weights ------------------------------
__global__ void k_dw(const float* __restrict__ dw_w2, const float* __restrict__ dw_b2) {
    int idx = blockIdx.x*blockDim.x + threadIdx.x;
    if (idx >= BB*64*64) return;
    int c = idx & 63;
    int o = (idx >> 6) & 63;
    int b = idx >> 12;
    const float inv = 1.f/(float)HWN;
    float s = dw_b2[o*64 + c];
    const float* wrow = &dw_w2[(o*64 + c)*64];
    const float* hm = &g_hsum[b*64];
    #pragma unroll 8
    for (int ic = 0; ic < 64; ic++) s += hm[ic]*inv*wrow[ic];
    g_dwT[(b*64 + c)*64 + o] = s;
}

// ---------------- conv2 tensor GEMM + guided combine ------------------------
// 12 warps, each m48 x n64; C tile 576 x 64, K = 576
__global__ void __launch_bounds__(384, 1) k_conv2g(const float* __restrict__ input,
                                                   const float* __restrict__ cw_b2) {
    extern __shared__ float smf[];
    float* scw = smf;                                // [576][65]
    __half* sB = (__half*)(smf + 576*65);            // [3][66][72]
    int tid = threadIdx.x, lane = tid & 31, w = tid >> 5;
    int x0 = blockIdx.x * 64;
    int h  = blockIdx.y;
    int b  = blockIdx.z;

    {   // stage B tile from g_tt
        uint* sBu = (uint*)sB;
        const uint* tt = (const uint*)g_tt;
        for (int i = tid; i < 3*66*32; i += 384) {
            int u = i & 31;
            int rest = i >> 5;
            int xi = rest % 66;
            int r  = rest / 66;
            int hh = h - 1 + r, xx = x0 - 1 + xi;
            uint v = 0;
            if (hh >= 0 && hh < HH && xx >= 0 && xx < WWI)
                v = tt[((((b*HH + hh)*WWI) + xx) << 5) + u];
            sBu[(r*66 + xi)*36 + u] = v;
        }
    }
    __syncthreads();

    int g = lane >> 2, t = lane & 3;
    uint sb32 = (uint)__cvta_generic_to_shared(sB);
    int row_off = (lane & 7) + ((lane & 16) ? 8 : 0);
    int col_off = (lane & 8) ? 8 : 0;

    float acc[3][8][4];
    #pragma unroll
    for (int mt = 0; mt < 3; mt++)
        #pragma unroll
        for (int nt = 0; nt < 8; nt++)
            #pragma unroll
            for (int q = 0; q < 4; q++) acc[mt][nt][q] = 0.f;

    uint4 A[2][3];
    {
        int base = ((0*4 + 0)*36 + w*3)*32 + lane;
        A[0][0] = g_w2p[base]; A[0][1] = g_w2p[base+32]; A[0][2] = g_w2p[base+64];
    }
    for (int ch = 0; ch < 36; ch++) {
        int cur = ch & 1;
        if (ch + 1 < 36) {
            int base = ((ch+1)*36 + w*3)*32 + lane;   // (tap*4+cc)=ch+1 flattened
            A[cur^1][0] = g_w2p[base]; A[cur^1][1] = g_w2p[base+32]; A[cur^1][2] = g_w2p[base+64];
        }
        int tap = ch >> 2, cc = ch & 3;
        int r = tap / 3, s = tap - r*3;
        int kc = cc*16;
        uint badd = sb32 + 2*(((r*66 + s + row_off)*72) + kc + col_off);
        #pragma unroll
        for (int p = 0; p < 4; p++) {
            uint b0,b1,b2,b3;
            ldsm4(b0,b1,b2,b3, badd + 2*(p*16*72));
            mma16816(acc[0][2*p],   (const uint*)&A[cur][0], b0, b1);
            mma16816(acc[1][2*p],   (const uint*)&A[cur][1], b0, b1);
            mma16816(acc[2][2*p],   (const uint*)&A[cur][2], b0, b1);
            mma16816(acc[0][2*p+1], (const uint*)&A[cur][0], b2, b3);
            mma16816(acc[1][2*p+1], (const uint*)&A[cur][1], b2, b3);
            mma16816(acc[2][2*p+1], (const uint*)&A[cur][2], b2, b3);
        }
    }

    // store C tile (+bias) to smem slab
    #pragma unroll
    for (int mt = 0; mt < 3; mt++) {
        int oc0 = w*48 + mt*16 + g, oc1 = oc0 + 8;
        float bv0 = cw_b2[oc0], bv1 = cw_b2[oc1];
        #pragma unroll
        for (int nt = 0; nt < 8; nt++) {
            int x = nt*8 + 2*t;
            scw[oc0*65 + x]     = acc[mt][nt][0] + bv0;
            scw[oc0*65 + x + 1] = acc[mt][nt][1] + bv0;
            scw[oc1*65 + x]     = acc[mt][nt][2] + bv1;
            scw[oc1*65 + x + 1] = acc[mt][nt][3] + bv1;
        }
    }
    __syncthreads();

    // guided combine
    for (int idx = tid; idx < 4096; idx += 384) {
        int c = idx >> 6, x = idx & 63;
        int gx = x0 + x;
        float y = 0.f;
        #pragma unroll
        for (int kh = 0; kh < 3; kh++) {
            int hh = h - 1 + kh;
            if (hh < 0 || hh >= HH) continue;
            const float* rowp = input + ((b*64 + c)*HH + hh)*WWI;
            #pragma unroll
            for (int kw = 0; kw < 3; kw++) {
                int ww = gx - 1 + kw;
                if (ww < 0 || ww >= WWI) continue;
                y += scw[(9*c + kh*3 + kw)*65 + x] * rowp[ww];
            }
        }
        g_y[(b*64 + c)*HWN + h*WWI + gx] = y;
    }
}

// ---------------- per-sample 1x1 (einsum) -----------------------------------
__global__ void k_einsum() {
    __shared__ float sdw[4096];
    int tid = threadIdx.x;        // 256
    int h = blockIdx.x & 255;
    int b = blockIdx.x >> 8;
    for (int i = tid; i < 4096; i += 256)
        sdw[i] = g_dwT[b*4096 + i];
    __syncthreads();

    const float* yp = &g_y[(size_t)(b*64)*HWN + h*WWI + tid];
    float accz[64];
    #pragma unroll
    for (int o = 0; o < 64; o++) accz[o] = 0.f;
    #pragma unroll 4
    for (int c = 0; c < 64; c++) {
        float yv = yp[(size_t)c*HWN];
        const float4* dp = (const float4*)&sdw[c*64];
        #pragma unroll
        for (int o4 = 0; o4 < 16; o4++) {
            float4 d = dp[o4];
            accz[o4*4+0] += yv*d.x;
            accz[o4*4+1] += yv*d.y;
            accz[o4*4+2] += yv*d.z;
            accz[o4*4+3] += yv*d.w;
        }
    }
    #pragma unroll
    for (int o = 0; o < 64; o++)
        g_z[(b*64 + o)*HWN + h*WWI + tid] = accz[o];
}

// ---------------- BN ---------------------------------------------------------
__global__ void k_stats() {
    int o = blockIdx.x >> 2, part = blockIdx.x & 3;
    float s = 0.f, s2 = 0.f;
    for (int b = 0; b < BB; b++) {
        const float* p = &g_z[(b*64 + o)*HWN + part*16384];
        for (int i = threadIdx.x; i < 16384; i += 256) {
            float v = p[i]; s += v; s2 += v*v;
        }
    }
    __shared__ float r1[256], r2[256];
    r1[threadIdx.x] = s; r2[threadIdx.x] = s2; __syncthreads();
    for (int k = 128; k > 0; k >>= 1) {
        if (threadIdx.x < k) { r1[threadIdx.x] += r1[threadIdx.x + k]; r2[threadIdx.x] += r2[threadIdx.x + k]; }
        __syncthreads();
    }
    if (threadIdx.x == 0) { atomicAdd(&g_sum[o], r1[0]); atomicAdd(&g_sumsq[o], r2[0]); }
}

__global__ void k_bn(const float* __restrict__ gamma, const float* __restrict__ beta,
                     float* __restrict__ out) {
    const float invN = 1.f/(float)(BB*HWN);
    int idx = blockIdx.x*blockDim.x + threadIdx.x;
    int stride = gridDim.x*blockDim.x;
    int total4 = BB*64*HWN/4;
    const float4* zp = (const float4*)g_z;
    float4* op = (float4*)out;
    for (int i = idx; i < total4; i += stride) {
        int o = (i >> 14) & 63;
        float mu  = g_sum[o]*invN;
        float var = g_sumsq[o]*invN - mu*mu;
        float rs  = rsqrtf(var + EPSF);
        float ga = gamma[o]*rs, be = beta[o];
        float4 z = zp[i];
        float4 r;
        r.x = fmaxf((z.x - mu)*ga + be, 0.f);
        r.y = fmaxf((z.y - mu)*ga + be, 0.f);
        r.z = fmaxf((z.z - mu)*ga + be, 0.f);
        r.w = fmaxf((z.w - mu)*ga + be, 0.f);
        op[i] = r;
    }
}

// ---------------- launch -----------------------------------------------------
extern "C" void kernel_launch(void* const* d_in, const int* in_sizes, int n_in,
                              void* d_out, int out_size) {
    const float* input    = (const float*)d_in[0];
    const float* guidance = (const float*)d_in[1];
    const float* cw_w1    = (const float*)d_in[2];
    const float* cw_b1    = (const float*)d_in[3];
    const float* cw_w2    = (const float*)d_in[4];
    const float* cw_b2    = (const float*)d_in[5];
    const float* dw_w1    = (const float*)d_in[6];
    const float* dw_b1    = (const float*)d_in[7];
    const float* dw_w2    = (const float*)d_in[8];
    const float* dw_b2    = (const float*)d_in[9];
    const float* bn_gamma = (const float*)d_in[10];
    const float* bn_beta  = (const float*)d_in[11];
    float* out = (float*)d_out;

    const int smem1 = 3*66*136*2;                    // 53856
    const int smem2 = 576*65*4 + 3*66*72*2;          // 178272
    cudaFuncSetAttribute(k_conv1,  cudaFuncAttributeMaxDynamicSharedMemorySize, smem1);
    cudaFuncSetAttribute(k_conv2g, cudaFuncAttributeMaxDynamicSharedMemorySize, smem2);

    k_zero<<<1, 256>>>();
    k_wp1<<<(9*8*8*32 + 255)/256, 256>>>(cw_w1, dw_w1);
    k_wp2<<<(9*4*36*32 + 255)/256, 256>>>(cw_w2);
    k_xt<<<dim3(8, 256, 2), 256>>>(input, guidance);
    k_conv1<<<dim3(4, 256, 2), 256, smem1>>>(cw_b1, dw_b1);
    k_dw<<<(BB*64*64 + 255)/256, 256>>>(dw_w2, dw_b2);
    k_conv2g<<<dim3(4, 256, 2), 384, smem2>>>(input, cw_b2);
    k_einsum<<<512, 256>>>();
    k_stats<<<256, 256>>>();
    k_bn<<<1024, 256>>>(bn_gamma, bn_beta, out);
}